// round 7
// baseline (speedup 1.0000x reference)
#include <cuda_runtime.h>
#include <cuda_bf16.h>
#include <math.h>

// DynamicVoxelizer: B=8, N=1e6, C=4.  (bitwise-exact vs XLA reference)
// Output layout (float32):
//   [0)          points_out    32,000,000
//   [32000000)   voxel_coords  24,000,000  (z,y,x; -1 if invalid)
//   [56000000)   point_idxes    8,000,000  (n in batch; -1 if invalid)
//   [64000000)   point_offsets 24,000,000  (xyz - center; 0 if invalid)
//   [88000000)   valid          8,000,000  (1.0/0.0)
//
// NUMERICS: XLA rewrites (x - pmin) / vs -> (x - pmin) * rn(1/vs);
// rn(1/0.1f)==10.0f, rn(1/0.2f)==5.0f exactly. Explicit __fmul_rn/__fadd_rn
// reproduce the reference bit-exactly (verified rel_err == 0.0 in R5).
//
// PERF: 4 points/thread so every store is a 128-bit STG (3-wide arrays pack
// to 3x float4 per thread at 48B-aligned offsets); streaming ld/st hints
// (.cs) keep the write-once / read-once streams from thrashing L2.

#define BN_TOTAL   8000000
#define N_PER_B    1000000
#define PTS_PER_T  4
#define NTHREADS   (BN_TOTAL / PTS_PER_T)
#define O_COORDS   32000000ull
#define O_IDX      56000000ull
#define O_OFFS     64000000ull
#define O_VALID    88000000ull

__global__ __launch_bounds__(256)
void voxelizer_kernel(const float4* __restrict__ pts, float* __restrict__ out)
{
    int t = blockIdx.x * blockDim.x + threadIdx.x;
    if (t >= NTHREADS) return;
    int j0 = t * PTS_PER_T;            // first point index for this thread

    float4 p[PTS_PER_T];
    #pragma unroll
    for (int k = 0; k < PTS_PER_T; k++)
        p[k] = __ldcs(&pts[j0 + k]);

    float fx[PTS_PER_T], fy[PTS_PER_T], fz[PTS_PER_T];
    float vflag[PTS_PER_T];
    bool  valid[PTS_PER_T];

    #pragma unroll
    for (int k = 0; k < PTS_PER_T; k++) {
        bool nn = !(isnan(p[k].x) || isnan(p[k].y) || isnan(p[k].z) || isnan(p[k].w));
        fx[k] = floorf(__fmul_rn(__fadd_rn(p[k].x, 51.2f), 10.0f));
        fy[k] = floorf(__fmul_rn(__fadd_rn(p[k].y, 51.2f), 10.0f));
        fz[k] = floorf(__fmul_rn(__fadd_rn(p[k].z,  5.0f),  5.0f));
        bool in_range = (fx[k] >= 0.0f) & (fx[k] < 1024.0f)
                      & (fy[k] >= 0.0f) & (fy[k] < 1024.0f)
                      & (fz[k] >= 0.0f) & (fz[k] < 40.0f);
        valid[k] = nn && in_range;
        vflag[k] = valid[k] ? 1.0f : 0.0f;
    }

    // ---- points_out: 4x float4 ----
    #pragma unroll
    for (int k = 0; k < PTS_PER_T; k++) {
        float4 po = valid[k] ? p[k] : make_float4(0.f, 0.f, 0.f, 0.f);
        __stcs(&reinterpret_cast<float4*>(out)[j0 + k], po);
    }

    // ---- voxel_coords: 12 floats (z,y,x per point), 3x float4, 48B-aligned ----
    {
        float c[12];
        #pragma unroll
        for (int k = 0; k < PTS_PER_T; k++) {
            c[3*k + 0] = valid[k] ? fz[k] : -1.0f;
            c[3*k + 1] = valid[k] ? fy[k] : -1.0f;
            c[3*k + 2] = valid[k] ? fx[k] : -1.0f;
        }
        float4* dst = reinterpret_cast<float4*>(out + O_COORDS + 12ull * (unsigned)t);
        __stcs(&dst[0], make_float4(c[0], c[1], c[2],  c[3]));
        __stcs(&dst[1], make_float4(c[4], c[5], c[6],  c[7]));
        __stcs(&dst[2], make_float4(c[8], c[9], c[10], c[11]));
    }

    // ---- point_idxes: 4 floats = 1 float4 ----
    {
        // N_PER_B divisible by 4 -> all 4 points share a batch
        int n0 = j0 - (j0 / N_PER_B) * N_PER_B;
        float4 idx = make_float4(
            valid[0] ? (float)(n0 + 0) : -1.0f,
            valid[1] ? (float)(n0 + 1) : -1.0f,
            valid[2] ? (float)(n0 + 2) : -1.0f,
            valid[3] ? (float)(n0 + 3) : -1.0f);
        __stcs(reinterpret_cast<float4*>(out + O_IDX + 4ull * (unsigned)t), idx);
    }

    // ---- point_offsets: 12 floats, 3x float4, 48B-aligned ----
    {
        float o[12];
        #pragma unroll
        for (int k = 0; k < PTS_PER_T; k++) {
            // centers = (cf*vs + pmin) + vs*0.5, exact f32, reference op order
            float cxc = __fadd_rn(__fadd_rn(__fmul_rn(fx[k], 0.1f), -51.2f), 0.05f);
            float cyc = __fadd_rn(__fadd_rn(__fmul_rn(fy[k], 0.1f), -51.2f), 0.05f);
            float czc = __fadd_rn(__fadd_rn(__fmul_rn(fz[k], 0.2f),  -5.0f), 0.1f);
            o[3*k + 0] = valid[k] ? __fadd_rn(p[k].x, -cxc) : 0.0f;
            o[3*k + 1] = valid[k] ? __fadd_rn(p[k].y, -cyc) : 0.0f;
            o[3*k + 2] = valid[k] ? __fadd_rn(p[k].z, -czc) : 0.0f;
        }
        float4* dst = reinterpret_cast<float4*>(out + O_OFFS + 12ull * (unsigned)t);
        __stcs(&dst[0], make_float4(o[0], o[1], o[2],  o[3]));
        __stcs(&dst[1], make_float4(o[4], o[5], o[6],  o[7]));
        __stcs(&dst[2], make_float4(o[8], o[9], o[10], o[11]));
    }

    // ---- valid: 4 floats = 1 float4 ----
    __stcs(reinterpret_cast<float4*>(out + O_VALID + 4ull * (unsigned)t),
           make_float4(vflag[0], vflag[1], vflag[2], vflag[3]));
}

extern "C" void kernel_launch(void* const* d_in, const int* in_sizes, int n_in,
                              void* d_out, int out_size)
{
    const float4* pts = (const float4*)d_in[0];
    float* out = (float*)d_out;
    int threads = 256;
    int blocks = (NTHREADS + threads - 1) / threads;
    voxelizer_kernel<<<blocks, threads>>>(pts, out);
}

// round 8
// speedup vs baseline: 1.4436x; 1.4436x over previous
#include <cuda_runtime.h>
#include <cuda_bf16.h>
#include <math.h>

// DynamicVoxelizer: B=8, N=1e6, C=4.  (bitwise-exact vs XLA reference, R5)
// Output layout (float32):
//   [0)          points_out    32,000,000
//   [32000000)   voxel_coords  24,000,000  (z,y,x; -1 if invalid)
//   [56000000)   point_idxes    8,000,000  (n in batch; -1 if invalid)
//   [64000000)   point_offsets 24,000,000  (xyz - center; 0 if invalid)
//   [88000000)   valid          8,000,000  (1.0/0.0)
//
// NUMERICS: XLA rewrites (x - pmin)/vs -> (x - pmin)*rn(1/vs);
// rn(1/0.1f)==10.0f, rn(1/0.2f)==5.0f exactly. Explicit __fmul_rn/__fadd_rn
// reproduce the reference bit-exactly (rel_err == 0.0 verified in R5).
//
// PERF (R7): 1 point/thread (all global accesses warp-coalesced), with the
// 3-wide and scalar outputs staged through 8KB smem and drained as flat
// coalesced STG.128 runs — 3 x 128-bit stores per thread total instead of
// 1 x STG.128 + 8 x STG.32.

#define BN_TOTAL   8000000
#define N_PER_B    1000000
#define BLK        256
#define O_COORDS   32000000ull
#define O_IDX      56000000ull
#define O_OFFS     64000000ull
#define O_VALID    88000000ull

// smem layout (floats): [0,768) coords, [768,1536) offsets, [1536,1792) idx, [1792,2048) valid
#define S_COORDS   0
#define S_OFFS     768
#define S_IDX      1536
#define S_VALID    1792

__global__ __launch_bounds__(BLK)
void voxelizer_kernel(const float4* __restrict__ pts, float* __restrict__ out)
{
    __shared__ float s[2048];   // 8 KB

    const int tid = threadIdx.x;
    const int b   = blockIdx.x;
    const int i   = b * BLK + tid;          // global point index (grid covers exactly 8M)

    float4 p = pts[i];

    bool nn = !(isnan(p.x) || isnan(p.y) || isnan(p.z) || isnan(p.w));

    // cf = floor((xyz - pmin) * rn(1/vs));  rn(1/0.1f)=10.0f, rn(1/0.2f)=5.0f (exact)
    float fx = floorf(__fmul_rn(__fadd_rn(p.x, 51.2f), 10.0f));
    float fy = floorf(__fmul_rn(__fadd_rn(p.y, 51.2f), 10.0f));
    float fz = floorf(__fmul_rn(__fadd_rn(p.z,  5.0f),  5.0f));

    bool in_range = (fx >= 0.0f) & (fx < 1024.0f)
                  & (fy >= 0.0f) & (fy < 1024.0f)
                  & (fz >= 0.0f) & (fz < 40.0f);
    bool valid = nn && in_range;

    // centers = (cf*vs + pmin) + vs*0.5, exact f32, reference op order
    float cxc = __fadd_rn(__fadd_rn(__fmul_rn(fx, 0.1f), -51.2f), 0.05f);
    float cyc = __fadd_rn(__fadd_rn(__fmul_rn(fy, 0.1f), -51.2f), 0.05f);
    float czc = __fadd_rn(__fadd_rn(__fmul_rn(fz, 0.2f),  -5.0f), 0.1f);

    // ---- points_out: direct coalesced STG.128 ----
    float4 po = valid ? p : make_float4(0.f, 0.f, 0.f, 0.f);
    reinterpret_cast<float4*>(out)[i] = po;

    // ---- stage coords (z,y,x), offsets, idx, valid into smem ----
    // stride-3 STS: odd stride -> conflict-free
    s[S_COORDS + 3*tid + 0] = valid ? fz : -1.0f;
    s[S_COORDS + 3*tid + 1] = valid ? fy : -1.0f;
    s[S_COORDS + 3*tid + 2] = valid ? fx : -1.0f;

    s[S_OFFS + 3*tid + 0] = valid ? __fadd_rn(p.x, -cxc) : 0.0f;
    s[S_OFFS + 3*tid + 1] = valid ? __fadd_rn(p.y, -cyc) : 0.0f;
    s[S_OFFS + 3*tid + 2] = valid ? __fadd_rn(p.z, -czc) : 0.0f;

    int n = i - (i / N_PER_B) * N_PER_B;
    s[S_IDX   + tid] = valid ? (float)n : -1.0f;
    s[S_VALID + tid] = valid ? 1.0f : 0.0f;

    __syncthreads();

    // ---- drain: 512 float4 per block, 2 per thread, fully coalesced ----
    const unsigned ub = (unsigned)b;
    #pragma unroll
    for (int pass = 0; pass < 2; pass++) {
        int q = tid + pass * BLK;           // 0..511
        float4 v;
        float4* dst;
        if (q < 192) {
            v   = *reinterpret_cast<const float4*>(&s[S_COORDS + 4*q]);
            dst = reinterpret_cast<float4*>(out + O_COORDS + 768ull*ub) + q;
        } else if (q < 384) {
            int q2 = q - 192;
            v   = *reinterpret_cast<const float4*>(&s[S_OFFS + 4*q2]);
            dst = reinterpret_cast<float4*>(out + O_OFFS + 768ull*ub) + q2;
        } else if (q < 448) {
            int q2 = q - 384;
            v   = *reinterpret_cast<const float4*>(&s[S_IDX + 4*q2]);
            dst = reinterpret_cast<float4*>(out + O_IDX + 256ull*ub) + q2;
        } else {
            int q2 = q - 448;
            v   = *reinterpret_cast<const float4*>(&s[S_VALID + 4*q2]);
            dst = reinterpret_cast<float4*>(out + O_VALID + 256ull*ub) + q2;
        }
        *dst = v;
    }
}

extern "C" void kernel_launch(void* const* d_in, const int* in_sizes, int n_in,
                              void* d_out, int out_size)
{
    const float4* pts = (const float4*)d_in[0];
    float* out = (float*)d_out;
    voxelizer_kernel<<<BN_TOTAL / BLK, BLK>>>(pts, out);
}

// round 9
// speedup vs baseline: 1.4596x; 1.0110x over previous
#include <cuda_runtime.h>
#include <cuda_bf16.h>
#include <math.h>

// DynamicVoxelizer: B=8, N=1e6, C=4.  (bitwise-exact vs XLA reference, R5)
// Output layout (float32):
//   [0)          points_out    32,000,000
//   [32000000)   voxel_coords  24,000,000  (z,y,x; -1 if invalid)
//   [56000000)   point_idxes    8,000,000  (n in batch; -1 if invalid)
//   [64000000)   point_offsets 24,000,000  (xyz - center; 0 if invalid)
//   [88000000)   valid          8,000,000  (1.0/0.0)
//
// NUMERICS: XLA rewrites (x - pmin)/vs -> (x - pmin)*rn(1/vs);
// rn(1/0.1f)==10.0f, rn(1/0.2f)==5.0f exactly. Explicit __fmul_rn/__fadd_rn
// reproduce the reference bit-exactly (rel_err == 0.0, R5/R7).
//
// PERF (R8): R7 structure (1 pt/thread, smem-staged 128-bit drains) +
// streaming cache hints (__ldcs/__stcs) — all streams are read-once /
// write-once against a 126MB L2, so evict-first stops pure pollution.

#define BN_TOTAL   8000000
#define N_PER_B    1000000
#define BLK        256
#define O_COORDS   32000000ull
#define O_IDX      56000000ull
#define O_OFFS     64000000ull
#define O_VALID    88000000ull

// smem layout (floats): [0,768) coords, [768,1536) offsets, [1536,1792) idx, [1792,2048) valid
#define S_COORDS   0
#define S_OFFS     768
#define S_IDX      1536
#define S_VALID    1792

__global__ __launch_bounds__(BLK)
void voxelizer_kernel(const float4* __restrict__ pts, float* __restrict__ out)
{
    __shared__ float s[2048];   // 8 KB

    const int tid = threadIdx.x;
    const int b   = blockIdx.x;
    const int i   = b * BLK + tid;          // grid covers exactly 8M points

    float4 p = __ldcs(&pts[i]);

    bool nn = !(isnan(p.x) || isnan(p.y) || isnan(p.z) || isnan(p.w));

    // cf = floor((xyz - pmin) * rn(1/vs));  rn(1/0.1f)=10.0f, rn(1/0.2f)=5.0f (exact)
    float fx = floorf(__fmul_rn(__fadd_rn(p.x, 51.2f), 10.0f));
    float fy = floorf(__fmul_rn(__fadd_rn(p.y, 51.2f), 10.0f));
    float fz = floorf(__fmul_rn(__fadd_rn(p.z,  5.0f),  5.0f));

    bool in_range = (fx >= 0.0f) & (fx < 1024.0f)
                  & (fy >= 0.0f) & (fy < 1024.0f)
                  & (fz >= 0.0f) & (fz < 40.0f);
    bool valid = nn && in_range;

    // centers = (cf*vs + pmin) + vs*0.5, exact f32, reference op order
    float cxc = __fadd_rn(__fadd_rn(__fmul_rn(fx, 0.1f), -51.2f), 0.05f);
    float cyc = __fadd_rn(__fadd_rn(__fmul_rn(fy, 0.1f), -51.2f), 0.05f);
    float czc = __fadd_rn(__fadd_rn(__fmul_rn(fz, 0.2f),  -5.0f), 0.1f);

    // ---- points_out: direct coalesced STG.128, evict-first ----
    float4 po = valid ? p : make_float4(0.f, 0.f, 0.f, 0.f);
    __stcs(&reinterpret_cast<float4*>(out)[i], po);

    // ---- stage coords (z,y,x), offsets, idx, valid into smem ----
    // stride-3 STS: odd stride -> conflict-free
    s[S_COORDS + 3*tid + 0] = valid ? fz : -1.0f;
    s[S_COORDS + 3*tid + 1] = valid ? fy : -1.0f;
    s[S_COORDS + 3*tid + 2] = valid ? fx : -1.0f;

    s[S_OFFS + 3*tid + 0] = valid ? __fadd_rn(p.x, -cxc) : 0.0f;
    s[S_OFFS + 3*tid + 1] = valid ? __fadd_rn(p.y, -cyc) : 0.0f;
    s[S_OFFS + 3*tid + 2] = valid ? __fadd_rn(p.z, -czc) : 0.0f;

    int n = i - (i / N_PER_B) * N_PER_B;
    s[S_IDX   + tid] = valid ? (float)n : -1.0f;
    s[S_VALID + tid] = valid ? 1.0f : 0.0f;

    __syncthreads();

    // ---- drain: 512 float4 per block, 2 per thread, fully coalesced ----
    const unsigned ub = (unsigned)b;
    #pragma unroll
    for (int pass = 0; pass < 2; pass++) {
        int q = tid + pass * BLK;           // 0..511
        float4 v;
        float4* dst;
        if (q < 192) {
            v   = *reinterpret_cast<const float4*>(&s[S_COORDS + 4*q]);
            dst = reinterpret_cast<float4*>(out + O_COORDS + 768ull*ub) + q;
        } else if (q < 384) {
            int q2 = q - 192;
            v   = *reinterpret_cast<const float4*>(&s[S_OFFS + 4*q2]);
            dst = reinterpret_cast<float4*>(out + O_OFFS + 768ull*ub) + q2;
        } else if (q < 448) {
            int q2 = q - 384;
            v   = *reinterpret_cast<const float4*>(&s[S_IDX + 4*q2]);
            dst = reinterpret_cast<float4*>(out + O_IDX + 256ull*ub) + q2;
        } else {
            int q2 = q - 448;
            v   = *reinterpret_cast<const float4*>(&s[S_VALID + 4*q2]);
            dst = reinterpret_cast<float4*>(out + O_VALID + 256ull*ub) + q2;
        }
        __stcs(dst, v);
    }
}

extern "C" void kernel_launch(void* const* d_in, const int* in_sizes, int n_in,
                              void* d_out, int out_size)
{
    const float4* pts = (const float4*)d_in[0];
    float* out = (float*)d_out;
    voxelizer_kernel<<<BN_TOTAL / BLK, BLK>>>(pts, out);
}